// round 3
// baseline (speedup 1.0000x reference)
#include <cuda_runtime.h>

#define NN   512
#define HDIM 128
#define NH   8
#define MDIM 256
#define TI   4
#define TJ   16
#define EG   64      // edges per tile = TI*TJ
#define JS   4       // j splits
#define SAPAD 260    // padded row stride for sA (avoid bank conflicts)
#define SATPAD 65    // padded row stride for transposed buffer

// ---- scratch (device globals; no allocation allowed) ----
__device__ float g_A[NN * MDIM];                 // hc @ We0[8:200]
__device__ float g_B[NN * MDIM];                 // hc @ We0[200:392]
__device__ float g_mi_part[JS * NN * MDIM];     // partial m_i per j-split
__device__ float g_shift_part[JS * NN * NH * 3];

__device__ __forceinline__ float siluf(float v) { return v / (1.0f + __expf(-v)); }
__device__ __forceinline__ float sigmf(float v) { return 1.0f / (1.0f + __expf(-v)); }

// ============================================================
// Kernel 1: per-node hc = [h, sqh], then A = hc@We0[8:200], B = hc@We0[200:392]
// ============================================================
__global__ void __launch_bounds__(256) node_pre_kernel(
    const float* __restrict__ x, const float* __restrict__ h,
    const float* __restrict__ We0)
{
    __shared__ float hc[192];
    __shared__ float sx[24];
    int n = blockIdx.x;
    int tid = threadIdx.x;
    if (tid < 24)  sx[tid] = x[n * 24 + tid];
    if (tid < 128) hc[tid] = h[n * 128 + tid];
    __syncthreads();
    if (tid < 64) {
        int h1 = tid >> 3, h2 = tid & 7;
        float s = 0.f;
        #pragma unroll
        for (int d = 0; d < 3; ++d) {
            float dx = sx[h1 * 3 + d] - sx[h2 * 3 + d];
            s += dx * dx;
        }
        hc[128 + tid] = s;
    }
    __syncthreads();
    float a = 0.f, b = 0.f;
    for (int k = 0; k < 192; ++k) {
        float v = hc[k];
        a = fmaf(v, We0[(8 + k) * 256 + tid], a);
        b = fmaf(v, We0[(200 + k) * 256 + tid], b);
    }
    g_A[n * 256 + tid] = a;
    g_B[n * 256 + tid] = b;
}

// ============================================================
// GEMM helper: OUT_regs = sIn[64 x 256] @ Wg[256 x 256]
// thread (ty,tx): rows ty*8+r, cols tx+32*c
// ============================================================
__device__ __forceinline__ void gemm64x256(
    const float* __restrict__ Wg, const float* sIn, float* sW,
    float acc[8][8], int tid)
{
    int ty = tid >> 5, tx = tid & 31;
    #pragma unroll
    for (int r = 0; r < 8; ++r)
        #pragma unroll
        for (int c = 0; c < 8; ++c) acc[r][c] = 0.f;

    for (int kb = 0; kb < 256; kb += 16) {
        __syncthreads();
        #pragma unroll
        for (int t = 0; t < 16; ++t) {
            int idx = t * 256 + tid;
            sW[idx] = Wg[kb * 256 + idx];   // row (kb+t), col tid
        }
        __syncthreads();
        #pragma unroll 2
        for (int kk = 0; kk < 16; ++kk) {
            float a[8], w[8];
            #pragma unroll
            for (int r = 0; r < 8; ++r) a[r] = sIn[(ty * 8 + r) * SAPAD + kb + kk];
            #pragma unroll
            for (int c = 0; c < 8; ++c) w[c] = sW[kk * 256 + tx + 32 * c];
            #pragma unroll
            for (int r = 0; r < 8; ++r)
                #pragma unroll
                for (int c = 0; c < 8; ++c) acc[r][c] = fmaf(a[r], w[c], acc[r][c]);
        }
    }
    __syncthreads();
}

// ============================================================
// Kernel 2: fused edge pipeline
// grid (NN/TI, JS), 256 threads
// ============================================================
__global__ void __launch_bounds__(256) edge_kernel(
    const float* __restrict__ x,
    const float* __restrict__ We0, const float* __restrict__ be0,
    const float* __restrict__ We1, const float* __restrict__ be1,
    const float* __restrict__ Winf, const float* __restrict__ binf,
    const float* __restrict__ Wx0, const float* __restrict__ bx0,
    const float* __restrict__ Wx1, const float* __restrict__ bx1,
    const float* __restrict__ Wxo, const float* __restrict__ bxo)
{
    extern __shared__ float sm[];
    float* sA    = sm;                      // 64*260
    float* sAT   = sA + EG * SAPAD;         // 256*65
    float* sW    = sAT + MDIM * SATPAD;     // 16*256
    float* sW0s  = sW + 16 * MDIM;          // 8*256  (We0 rows 0..7)
    float* sWxo  = sW0s + 8 * MDIM;         // 256*8
    float* sWinf = sWxo + MDIM * 8;         // 256
    float* sBe0  = sWinf + MDIM;            // 256
    float* sBe1  = sBe0 + MDIM;             // 256
    float* sBx0  = sBe1 + MDIM;             // 256
    float* sBx1  = sBx0 + MDIM;             // 256
    float* sBxo  = sBx1 + MDIM;             // 8
    float* sMi   = sBxo + 8;                // 4*256
    float* sSqn  = sMi + TI * MDIM;         // 64*8
    float* sXi   = sSqn + EG * NH;          // 96
    float* sXj   = sXi + 96;                // 384
    float* sE    = sXj + 384;               // 64
    float* sPx   = sE + EG;                 // 64*8
    float* sShift = sPx + EG * NH;          // 96

    int tid = threadIdx.x;
    int i0 = blockIdx.x * TI;
    int js = blockIdx.y;
    int ty = tid >> 5, tx = tid & 31;

    // ---- stage constants ----
    for (int t = tid; t < 8 * MDIM; t += 256) sW0s[t] = We0[t];
    for (int t = tid; t < MDIM * 8; t += 256) sWxo[t] = Wxo[t];
    sWinf[tid] = Winf[tid];
    sBe0[tid] = be0[tid];
    sBe1[tid] = be1[tid];
    sBx0[tid] = bx0[tid];
    sBx1[tid] = bx1[tid];
    if (tid < 8) sBxo[tid] = bxo[tid];
    for (int t = tid; t < TI * MDIM; t += 256) sMi[t] = 0.f;
    if (tid < 96) { sShift[tid] = 0.f; sXi[tid] = x[i0 * 24 + tid]; }
    float binf_v = binf[0];

    const int NJT = (NN / JS) / TJ;   // 8
    for (int jt = 0; jt < NJT; ++jt) {
        int j0 = js * (NN / JS) + jt * TJ;
        __syncthreads();   // protect sXj from prior iteration's shift-accum reads
        // FIX (R1): TJ*24 = 384 > 256 threads -> must stride this staging loop.
        for (int t = tid; t < TJ * 24; t += 256) sXj[t] = x[j0 * 24 + t];
        __syncthreads();

        // ---- sqn tile ----
        for (int q = tid; q < EG * NH; q += 256) {
            int e = q >> 3, hh = q & 7;
            int ti = e >> 4, tj = e & 15;
            float s = 0.f;
            #pragma unroll
            for (int d = 0; d < 3; ++d) {
                float dx = sXj[tj * 24 + hh * 3 + d] - sXi[ti * 24 + hh * 3 + d];
                s += dx * dx;
            }
            sSqn[q] = s;
        }
        __syncthreads();

        // ---- layer 1 via rank-combine: a1 = silu(A[j] + B[i] + be0 + sqn@We0[0:8]) ----
        {
            int t = tid;
            float bvals[TI], avals[TJ];
            #pragma unroll
            for (int ti = 0; ti < TI; ++ti) bvals[ti] = g_B[(i0 + ti) * MDIM + t] + sBe0[t];
            #pragma unroll
            for (int tj = 0; tj < TJ; ++tj) avals[tj] = g_A[(j0 + tj) * MDIM + t];
            #pragma unroll
            for (int e = 0; e < EG; ++e) {
                int ti = e >> 4, tj = e & 15;
                float v = avals[tj] + bvals[ti];
                #pragma unroll
                for (int hh = 0; hh < 8; ++hh)
                    v = fmaf(sSqn[e * 8 + hh], sW0s[hh * MDIM + t], v);
                sA[e * SAPAD + t] = siluf(v);
            }
        }
        __syncthreads();

        float acc[8][8];

        // ---- GEMM1: m = silu(a1 @ We1 + be1) -> sA ----
        gemm64x256(We1, sA, sW, acc, tid);
        #pragma unroll
        for (int r = 0; r < 8; ++r)
            #pragma unroll
            for (int c = 0; c < 8; ++c) {
                int row = ty * 8 + r, col = tx + 32 * c;
                sA[row * SAPAD + col] = siluf(acc[r][c] + sBe1[col]);
            }
        __syncthreads();

        // ---- e gate: sigmoid(m . Winf + binf), zero diagonal ----
        {
            int e = tid >> 2, p = tid & 3;
            float s = 0.f;
            #pragma unroll 8
            for (int u = 0; u < 64; ++u) {
                int k = p + 4 * u;
                s = fmaf(sA[e * SAPAD + k], sWinf[k], s);
            }
            s += __shfl_xor_sync(0xffffffffu, s, 1);
            s += __shfl_xor_sync(0xffffffffu, s, 2);
            if (p == 0) {
                int gi = i0 + (e >> 4), gj = j0 + (e & 15);
                sE[e] = (gi == gj) ? 0.f : sigmf(s + binf_v);
            }
        }
        __syncthreads();

        // ---- m_i accumulation (thread owns column tid) ----
        {
            int t = tid;
            #pragma unroll 8
            for (int e = 0; e < EG; ++e)
                sMi[(e >> 4) * MDIM + t] = fmaf(sA[e * SAPAD + t], sE[e], sMi[(e >> 4) * MDIM + t]);
        }
        __syncthreads();

        // ---- GEMM2: b1 = silu(m @ Wx0 + bx0) -> sA ----
        gemm64x256(Wx0, sA, sW, acc, tid);
        #pragma unroll
        for (int r = 0; r < 8; ++r)
            #pragma unroll
            for (int c = 0; c < 8; ++c) {
                int row = ty * 8 + r, col = tx + 32 * c;
                sA[row * SAPAD + col] = siluf(acc[r][c] + sBx0[col]);
            }
        __syncthreads();

        // ---- GEMM3: b2 = silu(b1 @ Wx1 + bx1) -> sAT (transposed) ----
        gemm64x256(Wx1, sA, sW, acc, tid);
        #pragma unroll
        for (int r = 0; r < 8; ++r)
            #pragma unroll
            for (int c = 0; c < 8; ++c) {
                int row = ty * 8 + r, col = tx + 32 * c;
                sAT[col * SATPAD + row] = siluf(acc[r][c] + sBx1[col]);
            }
        __syncthreads();

        // ---- px = b2 @ Wxo + bxo (per-edge 8 heads), zero diagonal ----
        {
            int hh = tid >> 5, lane = tid & 31;
            #pragma unroll
            for (int rep = 0; rep < 2; ++rep) {
                int e = lane + 32 * rep;
                float s = sBxo[hh];
                #pragma unroll 8
                for (int c = 0; c < MDIM; ++c)
                    s = fmaf(sAT[c * SATPAD + e], sWxo[c * 8 + hh], s);
                int gi = i0 + (e >> 4), gj = j0 + (e & 15);
                sPx[e * 8 + hh] = (gi == gj) ? 0.f : s;
            }
        }
        __syncthreads();

        // ---- shift accumulation ----
        if (tid < 96) {
            int ti = tid / 24, r = tid % 24, hh = r / 3, d = r % 3;
            float a = 0.f;
            #pragma unroll
            for (int tj = 0; tj < TJ; ++tj) {
                int e = ti * 16 + tj;
                float sq = sSqn[e * 8 + hh];
                float nrm = sqrtf(sq + 1e-8f) + 1.0f;
                float dn = sXj[tj * 24 + hh * 3 + d] - sXi[ti * 24 + hh * 3 + d];
                a = fmaf(sPx[e * 8 + hh], dn / nrm, a);
            }
            sShift[tid] += a;
        }
    }
    __syncthreads();

    // ---- write partials ----
    {
        int t = tid;
        #pragma unroll
        for (int ti = 0; ti < TI; ++ti)
            g_mi_part[(js * NN + i0 + ti) * MDIM + t] = sMi[ti * MDIM + t];
    }
    if (tid < 96) {
        int ti = tid / 24, r = tid % 24;
        g_shift_part[(js * NN + i0 + ti) * 24 + r] = sShift[tid];
    }
}

// ============================================================
// Kernel 3: x_new = x + (sum_js shift_part) / (N-1)
// ============================================================
__global__ void finalize_x_kernel(const float* __restrict__ x, float* __restrict__ out)
{
    int idx = blockIdx.x * 256 + threadIdx.x;
    if (idx < NN * NH * 3) {
        float s = 0.f;
        #pragma unroll
        for (int js = 0; js < JS; ++js) s += g_shift_part[js * NN * 24 + idx];
        out[idx] = x[idx] + s * (1.0f / (float)(NN - 1));
    }
}

// ============================================================
// Kernel 4: phi_h  (8 nodes per block)
// ============================================================
#define NPB 8
__global__ void __launch_bounds__(256) h_kernel(
    const float* __restrict__ h,
    const float* __restrict__ Wh0, const float* __restrict__ bh0,
    const float* __restrict__ Wh1, const float* __restrict__ bh1,
    const float* __restrict__ Who, const float* __restrict__ bho,
    float* __restrict__ out)
{
    __shared__ float sin_s[NPB][384];
    __shared__ float s1[NPB][256];
    __shared__ float s2[NPB][256];
    int tid = threadIdx.x;
    int nb = blockIdx.x * NPB;

    for (int t = tid; t < NPB * 256; t += 256) {
        int nn = t >> 8, c = t & 255;
        float mi = 0.f;
        #pragma unroll
        for (int js = 0; js < JS; ++js)
            mi += g_mi_part[(js * NN + nb + nn) * MDIM + c];
        sin_s[nn][c] = mi;
    }
    for (int t = tid; t < NPB * 128; t += 256) {
        int nn = t >> 7, c = t & 127;
        sin_s[nn][256 + c] = h[(nb + nn) * 128 + c];
    }
    __syncthreads();
    {
        float acc[NPB];
        #pragma unroll
        for (int nn = 0; nn < NPB; ++nn) acc[nn] = 0.f;
        for (int k = 0; k < 384; ++k) {
            float w = Wh0[k * 256 + tid];
            #pragma unroll
            for (int nn = 0; nn < NPB; ++nn) acc[nn] = fmaf(sin_s[nn][k], w, acc[nn]);
        }
        float b = bh0[tid];
        #pragma unroll
        for (int nn = 0; nn < NPB; ++nn) s1[nn][tid] = siluf(acc[nn] + b);
    }
    __syncthreads();
    {
        float acc[NPB];
        #pragma unroll
        for (int nn = 0; nn < NPB; ++nn) acc[nn] = 0.f;
        for (int k = 0; k < 256; ++k) {
            float w = Wh1[k * 256 + tid];
            #pragma unroll
            for (int nn = 0; nn < NPB; ++nn) acc[nn] = fmaf(s1[nn][k], w, acc[nn]);
        }
        float b = bh1[tid];
        #pragma unroll
        for (int nn = 0; nn < NPB; ++nn) s2[nn][tid] = siluf(acc[nn] + b);
    }
    __syncthreads();
    if (tid < 128) {
        float acc[NPB];
        #pragma unroll
        for (int nn = 0; nn < NPB; ++nn) acc[nn] = 0.f;
        for (int k = 0; k < 256; ++k) {
            float w = Who[k * 128 + tid];
            #pragma unroll
            for (int nn = 0; nn < NPB; ++nn) acc[nn] = fmaf(s2[nn][k], w, acc[nn]);
        }
        float b = bho[tid];
        #pragma unroll
        for (int nn = 0; nn < NPB; ++nn)
            out[NN * NH * 3 + (nb + nn) * 128 + tid] = h[(nb + nn) * 128 + tid] + acc[nn] + b;
    }
}

// ============================================================
extern "C" void kernel_launch(void* const* d_in, const int* in_sizes, int n_in,
                              void* d_out, int out_size)
{
    const float* x    = (const float*)d_in[0];
    const float* h    = (const float*)d_in[1];
    const float* We0  = (const float*)d_in[2];
    const float* be0  = (const float*)d_in[3];
    const float* We1  = (const float*)d_in[4];
    const float* be1  = (const float*)d_in[5];
    const float* Winf = (const float*)d_in[6];
    const float* binf = (const float*)d_in[7];
    const float* Wx0  = (const float*)d_in[8];
    const float* bx0  = (const float*)d_in[9];
    const float* Wx1  = (const float*)d_in[10];
    const float* bx1  = (const float*)d_in[11];
    const float* Wxo  = (const float*)d_in[12];
    const float* bxo  = (const float*)d_in[13];
    const float* Wh0  = (const float*)d_in[14];
    const float* bh0  = (const float*)d_in[15];
    const float* Wh1  = (const float*)d_in[16];
    const float* bh1  = (const float*)d_in[17];
    const float* Who  = (const float*)d_in[18];
    const float* bho  = (const float*)d_in[19];
    float* out = (float*)d_out;

    node_pre_kernel<<<NN, 256>>>(x, h, We0);

    const int smem_floats =
        EG * SAPAD + MDIM * SATPAD + 16 * MDIM + 8 * MDIM + MDIM * 8 +
        MDIM + 4 * MDIM + 8 + TI * MDIM + EG * NH + 96 + 384 + EG + EG * NH + 96;
    const int smem_bytes = smem_floats * 4;
    static int attr_set = 0;
    if (!attr_set) {
        cudaFuncSetAttribute(edge_kernel, cudaFuncAttributeMaxDynamicSharedMemorySize, smem_bytes);
        attr_set = 1;
    }
    edge_kernel<<<dim3(NN / TI, JS), 256, smem_bytes>>>(
        x, We0, be0, We1, be1, Winf, binf, Wx0, bx0, Wx1, bx1, Wxo, bxo);

    finalize_x_kernel<<<(NN * NH * 3 + 255) / 256, 256>>>(x, out);

    h_kernel<<<NN / NPB, 256>>>(h, Wh0, bh0, Wh1, bh1, Who, bho, out);
}

// round 5
// speedup vs baseline: 2.3206x; 2.3206x over previous
#include <cuda_runtime.h>
#include <cstdint>

#define NN   512
#define HDIM 128
#define NH   8
#define MDIM 256
#define TI   4
#define TJ   16
#define EG   64      // edges per tile = TI*TJ
#define JS   4       // j splits
#define SAPAD 260    // padded row stride for sA (conflict-free HMMA A loads: 4g+tg)
#define SATPAD 65    // padded row stride for transposed buffer
#define SWPAD 264    // padded row stride for sW (conflict-free HMMA B loads: 8tg+g)
#define KSTAGE 32    // weight rows staged per sync

// ---- scratch (device globals; no allocation allowed) ----
__device__ float g_A[NN * MDIM];                 // hc @ We0[8:200]
__device__ float g_B[NN * MDIM];                 // hc @ We0[200:392]
__device__ float g_mi_part[JS * NN * MDIM];     // partial m_i per j-split
__device__ float g_shift_part[JS * NN * NH * 3];

__device__ __forceinline__ float siluf(float v) { return v / (1.0f + __expf(-v)); }
__device__ __forceinline__ float sigmf(float v) { return 1.0f / (1.0f + __expf(-v)); }

__device__ __forceinline__ uint32_t f2tf32(float v) {
    uint32_t r;
    asm("cvt.rna.tf32.f32 %0, %1;" : "=r"(r) : "f"(v));
    return r;
}
__device__ __forceinline__ float tf32r(float v) { return __uint_as_float(f2tf32(v)); }

__device__ __forceinline__ void mma_tf32(float* d,
    uint32_t a0, uint32_t a1, uint32_t a2, uint32_t a3,
    uint32_t b0, uint32_t b1)
{
    asm volatile(
        "mma.sync.aligned.m16n8k8.row.col.f32.tf32.tf32.f32 "
        "{%0,%1,%2,%3}, {%4,%5,%6,%7}, {%8,%9}, {%0,%1,%2,%3};\n"
        : "+f"(d[0]), "+f"(d[1]), "+f"(d[2]), "+f"(d[3])
        : "r"(a0), "r"(a1), "r"(a2), "r"(a3), "r"(b0), "r"(b1));
}

// ============================================================
// Kernel 1: per-node hc = [h, sqh], then A = hc@We0[8:200], B = hc@We0[200:392]
// ============================================================
__global__ void __launch_bounds__(256) node_pre_kernel(
    const float* __restrict__ x, const float* __restrict__ h,
    const float* __restrict__ We0)
{
    __shared__ float hc[192];
    __shared__ float sx[24];
    int n = blockIdx.x;
    int tid = threadIdx.x;
    if (tid < 24)  sx[tid] = x[n * 24 + tid];
    if (tid < 128) hc[tid] = h[n * 128 + tid];
    __syncthreads();
    if (tid < 64) {
        int h1 = tid >> 3, h2 = tid & 7;
        float s = 0.f;
        #pragma unroll
        for (int d = 0; d < 3; ++d) {
            float dx = sx[h1 * 3 + d] - sx[h2 * 3 + d];
            s += dx * dx;
        }
        hc[128 + tid] = s;
    }
    __syncthreads();
    float a = 0.f, b = 0.f;
    for (int k = 0; k < 192; ++k) {
        float v = hc[k];
        a = fmaf(v, We0[(8 + k) * 256 + tid], a);
        b = fmaf(v, We0[(200 + k) * 256 + tid], b);
    }
    g_A[n * 256 + tid] = a;
    g_B[n * 256 + tid] = b;
}

// ============================================================
// HMMA GEMM helper: acc[mt][nt][4] = sIn[64 x 256] @ Wg[256 x 256] (tf32)
// Warp w owns output cols [32w, 32w+32). Per warp: 4 m-tiles(16) x 4 n-tiles(8).
// sIn values must already be tf32-rounded. Weights converted during staging.
// ============================================================
__device__ __forceinline__ void gemm64x256_hmma(
    const float* __restrict__ Wg, const float* sIn, float* sW,
    float acc[4][4][4], int tid)
{
    const int w = tid >> 5;
    const int lane = tid & 31;
    const int g = lane >> 2, tg = lane & 3;
    const int n0 = w * 32;

    #pragma unroll
    for (int mt = 0; mt < 4; ++mt)
        #pragma unroll
        for (int nt = 0; nt < 4; ++nt)
            #pragma unroll
            for (int c = 0; c < 4; ++c) acc[mt][nt][c] = 0.f;

    for (int kb = 0; kb < 256; kb += KSTAGE) {
        __syncthreads();
        #pragma unroll
        for (int t = 0; t < KSTAGE; ++t)
            sW[t * SWPAD + tid] = tf32r(Wg[(kb + t) * 256 + tid]);
        __syncthreads();

        #pragma unroll
        for (int kc = 0; kc < KSTAGE / 8; ++kc) {
            const int k0 = kc * 8;
            uint32_t a[4][4], b[4][2];
            #pragma unroll
            for (int mt = 0; mt < 4; ++mt) {
                const float* base = sIn + (mt * 16 + g) * SAPAD + kb + k0 + tg;
                a[mt][0] = __float_as_uint(base[0]);
                a[mt][1] = __float_as_uint(base[8 * SAPAD]);
                a[mt][2] = __float_as_uint(base[4]);
                a[mt][3] = __float_as_uint(base[8 * SAPAD + 4]);
            }
            #pragma unroll
            for (int nt = 0; nt < 4; ++nt) {
                const float* bb = sW + (k0 + tg) * SWPAD + n0 + nt * 8 + g;
                b[nt][0] = __float_as_uint(bb[0]);
                b[nt][1] = __float_as_uint(bb[4 * SWPAD]);
            }
            #pragma unroll
            for (int mt = 0; mt < 4; ++mt)
                #pragma unroll
                for (int nt = 0; nt < 4; ++nt)
                    mma_tf32(acc[mt][nt], a[mt][0], a[mt][1], a[mt][2], a[mt][3],
                             b[nt][0], b[nt][1]);
        }
    }
    __syncthreads();
}

// ============================================================
// Kernel 2: fused edge pipeline
// grid (NN/TI, JS), 256 threads
// ============================================================
__global__ void __launch_bounds__(256) edge_kernel(
    const float* __restrict__ x,
    const float* __restrict__ We0, const float* __restrict__ be0,
    const float* __restrict__ We1, const float* __restrict__ be1,
    const float* __restrict__ Winf, const float* __restrict__ binf,
    const float* __restrict__ Wx0, const float* __restrict__ bx0,
    const float* __restrict__ Wx1, const float* __restrict__ bx1,
    const float* __restrict__ Wxo, const float* __restrict__ bxo)
{
    extern __shared__ float sm[];
    float* sA    = sm;                      // 64*260
    float* sAT   = sA + EG * SAPAD;         // 256*65
    float* sW    = sAT + MDIM * SATPAD;     // 32*264
    float* sW0s  = sW + KSTAGE * SWPAD;     // 8*256  (We0 rows 0..7)
    float* sWxo  = sW0s + 8 * MDIM;         // 256*8
    float* sWinf = sWxo + MDIM * 8;         // 256
    float* sBe0  = sWinf + MDIM;            // 256
    float* sBe1  = sBe0 + MDIM;             // 256
    float* sBx0  = sBe1 + MDIM;             // 256
    float* sBx1  = sBx0 + MDIM;             // 256
    float* sBxo  = sBx1 + MDIM;             // 8
    float* sMi   = sBxo + 8;                // 4*256
    float* sSqn  = sMi + TI * MDIM;         // 64*8
    float* sXi   = sSqn + EG * NH;          // 96
    float* sXj   = sXi + 96;                // 384
    float* sE    = sXj + 384;               // 64
    float* sPx   = sE + EG;                 // 64*8
    float* sShift = sPx + EG * NH;          // 96

    int tid = threadIdx.x;
    int i0 = blockIdx.x * TI;
    int js = blockIdx.y;
    const int wlane = tid & 31;
    const int wg = wlane >> 2, wtg = wlane & 3;
    const int wn0 = (tid >> 5) * 32;

    // ---- stage constants ----
    for (int t = tid; t < 8 * MDIM; t += 256) sW0s[t] = We0[t];
    for (int t = tid; t < MDIM * 8; t += 256) sWxo[t] = Wxo[t];
    sWinf[tid] = Winf[tid];
    sBe0[tid] = be0[tid];
    sBe1[tid] = be1[tid];
    sBx0[tid] = bx0[tid];
    sBx1[tid] = bx1[tid];
    if (tid < 8) sBxo[tid] = bxo[tid];
    for (int t = tid; t < TI * MDIM; t += 256) sMi[t] = 0.f;
    if (tid < 96) { sShift[tid] = 0.f; sXi[tid] = x[i0 * 24 + tid]; }
    float binf_v = binf[0];

    const int NJT = (NN / JS) / TJ;   // 8
    for (int jt = 0; jt < NJT; ++jt) {
        int j0 = js * (NN / JS) + jt * TJ;
        __syncthreads();   // protect sXj from prior iteration's shift-accum reads
        for (int t = tid; t < TJ * 24; t += 256) sXj[t] = x[j0 * 24 + t];
        __syncthreads();

        // ---- sqn tile ----
        for (int q = tid; q < EG * NH; q += 256) {
            int e = q >> 3, hh = q & 7;
            int ti = e >> 4, tj = e & 15;
            float s = 0.f;
            #pragma unroll
            for (int d = 0; d < 3; ++d) {
                float dx = sXj[tj * 24 + hh * 3 + d] - sXi[ti * 24 + hh * 3 + d];
                s += dx * dx;
            }
            sSqn[q] = s;
        }
        __syncthreads();

        // ---- layer 1 via rank-combine: a1 = silu(A[j] + B[i] + be0 + sqn@We0[0:8]) ----
        // store tf32-rounded (input to HMMA GEMM1)
        {
            int t = tid;
            float bvals[TI], avals[TJ];
            #pragma unroll
            for (int ti = 0; ti < TI; ++ti) bvals[ti] = g_B[(i0 + ti) * MDIM + t] + sBe0[t];
            #pragma unroll
            for (int tj = 0; tj < TJ; ++tj) avals[tj] = g_A[(j0 + tj) * MDIM + t];
            #pragma unroll
            for (int e = 0; e < EG; ++e) {
                int ti = e >> 4, tj = e & 15;
                float v = avals[tj] + bvals[ti];
                #pragma unroll
                for (int hh = 0; hh < 8; ++hh)
                    v = fmaf(sSqn[e * 8 + hh], sW0s[hh * MDIM + t], v);
                sA[e * SAPAD + t] = tf32r(siluf(v));
            }
        }
        __syncthreads();

        float acc[4][4][4];

        // ---- GEMM1 (HMMA tf32): m = silu(a1 @ We1 + be1) -> sA (rounded) ----
        gemm64x256_hmma(We1, sA, sW, acc, tid);
        #pragma unroll
        for (int mt = 0; mt < 4; ++mt)
            #pragma unroll
            for (int nt = 0; nt < 4; ++nt)
                #pragma unroll
                for (int c = 0; c < 4; ++c) {
                    int row = mt * 16 + wg + ((c >= 2) ? 8 : 0);
                    int col = wn0 + nt * 8 + wtg * 2 + (c & 1);
                    sA[row * SAPAD + col] = tf32r(siluf(acc[mt][nt][c] + sBe1[col]));
                }
        __syncthreads();

        // ---- e gate: sigmoid(m . Winf + binf), zero diagonal ----
        {
            int e = tid >> 2, p = tid & 3;
            float s = 0.f;
            #pragma unroll 8
            for (int u = 0; u < 64; ++u) {
                int k = p + 4 * u;
                s = fmaf(sA[e * SAPAD + k], sWinf[k], s);
            }
            s += __shfl_xor_sync(0xffffffffu, s, 1);
            s += __shfl_xor_sync(0xffffffffu, s, 2);
            if (p == 0) {
                int gi = i0 + (e >> 4), gj = j0 + (e & 15);
                sE[e] = (gi == gj) ? 0.f : sigmf(s + binf_v);
            }
        }
        __syncthreads();

        // ---- m_i accumulation (thread owns column tid) ----
        {
            int t = tid;
            #pragma unroll 8
            for (int e = 0; e < EG; ++e)
                sMi[(e >> 4) * MDIM + t] = fmaf(sA[e * SAPAD + t], sE[e], sMi[(e >> 4) * MDIM + t]);
        }
        __syncthreads();

        // ---- GEMM2 (HMMA tf32): b1 = silu(m @ Wx0 + bx0) -> sA (rounded) ----
        gemm64x256_hmma(Wx0, sA, sW, acc, tid);
        #pragma unroll
        for (int mt = 0; mt < 4; ++mt)
            #pragma unroll
            for (int nt = 0; nt < 4; ++nt)
                #pragma unroll
                for (int c = 0; c < 4; ++c) {
                    int row = mt * 16 + wg + ((c >= 2) ? 8 : 0);
                    int col = wn0 + nt * 8 + wtg * 2 + (c & 1);
                    sA[row * SAPAD + col] = tf32r(siluf(acc[mt][nt][c] + sBx0[col]));
                }
        __syncthreads();

        // ---- GEMM3 (HMMA tf32): b2 = silu(b1 @ Wx1 + bx1) -> sAT (transposed, fp32) ----
        gemm64x256_hmma(Wx1, sA, sW, acc, tid);
        #pragma unroll
        for (int mt = 0; mt < 4; ++mt)
            #pragma unroll
            for (int nt = 0; nt < 4; ++nt)
                #pragma unroll
                for (int c = 0; c < 4; ++c) {
                    int row = mt * 16 + wg + ((c >= 2) ? 8 : 0);
                    int col = wn0 + nt * 8 + wtg * 2 + (c & 1);
                    sAT[col * SATPAD + row] = siluf(acc[mt][nt][c] + sBx1[col]);
                }
        __syncthreads();

        // ---- px = b2 @ Wxo + bxo (per-edge 8 heads), zero diagonal ----
        {
            int hh = tid >> 5, lane = tid & 31;
            #pragma unroll
            for (int rep = 0; rep < 2; ++rep) {
                int e = lane + 32 * rep;
                float s = sBxo[hh];
                #pragma unroll 8
                for (int c = 0; c < MDIM; ++c)
                    s = fmaf(sAT[c * SATPAD + e], sWxo[c * 8 + hh], s);
                int gi = i0 + (e >> 4), gj = j0 + (e & 15);
                sPx[e * 8 + hh] = (gi == gj) ? 0.f : s;
            }
        }
        __syncthreads();

        // ---- shift accumulation ----
        if (tid < 96) {
            int ti = tid / 24, r = tid % 24, hh = r / 3, d = r % 3;
            float a = 0.f;
            #pragma unroll
            for (int tj = 0; tj < TJ; ++tj) {
                int e = ti * 16 + tj;
                float sq = sSqn[e * 8 + hh];
                float nrm = sqrtf(sq + 1e-8f) + 1.0f;
                float dn = sXj[tj * 24 + hh * 3 + d] - sXi[ti * 24 + hh * 3 + d];
                a = fmaf(sPx[e * 8 + hh], dn / nrm, a);
            }
            sShift[tid] += a;
        }
    }
    __syncthreads();

    // ---- write partials ----
    {
        int t = tid;
        #pragma unroll
        for (int ti = 0; ti < TI; ++ti)
            g_mi_part[(js * NN + i0 + ti) * MDIM + t] = sMi[ti * MDIM + t];
    }
    if (tid < 96) {
        int ti = tid / 24, r = tid % 24;
        g_shift_part[(js * NN + i0 + ti) * 24 + r] = sShift[tid];
    }
}

// ============================================================
// Kernel 3: x_new = x + (sum_js shift_part) / (N-1)
// ============================================================
__global__ void finalize_x_kernel(const float* __restrict__ x, float* __restrict__ out)
{
    int idx = blockIdx.x * 256 + threadIdx.x;
    if (idx < NN * NH * 3) {
        float s = 0.f;
        #pragma unroll
        for (int js = 0; js < JS; ++js) s += g_shift_part[js * NN * 24 + idx];
        out[idx] = x[idx] + s * (1.0f / (float)(NN - 1));
    }
}

// ============================================================
// Kernel 4: phi_h  (8 nodes per block)
// ============================================================
#define NPB 8
__global__ void __launch_bounds__(256) h_kernel(
    const float* __restrict__ h,
    const float* __restrict__ Wh0, const float* __restrict__ bh0,
    const float* __restrict__ Wh1, const float* __restrict__ bh1,
    const float* __restrict__ Who, const float* __restrict__ bho,
    float* __restrict__ out)
{
    __shared__ float sin_s[NPB][384];
    __shared__ float s1[NPB][256];
    __shared__ float s2[NPB][256];
    int tid = threadIdx.x;
    int nb = blockIdx.x * NPB;

    for (int t = tid; t < NPB * 256; t += 256) {
        int nn = t >> 8, c = t & 255;
        float mi = 0.f;
        #pragma unroll
        for (int js = 0; js < JS; ++js)
            mi += g_mi_part[(js * NN + nb + nn) * MDIM + c];
        sin_s[nn][c] = mi;
    }
    for (int t = tid; t < NPB * 128; t += 256) {
        int nn = t >> 7, c = t & 127;
        sin_s[nn][256 + c] = h[(nb + nn) * 128 + c];
    }
    __syncthreads();
    {
        float acc[NPB];
        #pragma unroll
        for (int nn = 0; nn < NPB; ++nn) acc[nn] = 0.f;
        for (int k = 0; k < 384; ++k) {
            float w = Wh0[k * 256 + tid];
            #pragma unroll
            for (int nn = 0; nn < NPB; ++nn) acc[nn] = fmaf(sin_s[nn][k], w, acc[nn]);
        }
        float b = bh0[tid];
        #pragma unroll
        for (int nn = 0; nn < NPB; ++nn) s1[nn][tid] = siluf(acc[nn] + b);
    }
    __syncthreads();
    {
        float acc[NPB];
        #pragma unroll
        for (int nn = 0; nn < NPB; ++nn) acc[nn] = 0.f;
        for (int k = 0; k < 256; ++k) {
            float w = Wh1[k * 256 + tid];
            #pragma unroll
            for (int nn = 0; nn < NPB; ++nn) acc[nn] = fmaf(s1[nn][k], w, acc[nn]);
        }
        float b = bh1[tid];
        #pragma unroll
        for (int nn = 0; nn < NPB; ++nn) s2[nn][tid] = siluf(acc[nn] + b);
    }
    __syncthreads();
    if (tid < 128) {
        float acc[NPB];
        #pragma unroll
        for (int nn = 0; nn < NPB; ++nn) acc[nn] = 0.f;
        for (int k = 0; k < 256; ++k) {
            float w = Who[k * 128 + tid];
            #pragma unroll
            for (int nn = 0; nn < NPB; ++nn) acc[nn] = fmaf(s2[nn][k], w, acc[nn]);
        }
        float b = bho[tid];
        #pragma unroll
        for (int nn = 0; nn < NPB; ++nn)
            out[NN * NH * 3 + (nb + nn) * 128 + tid] = h[(nb + nn) * 128 + tid] + acc[nn] + b;
    }
}

// ============================================================
extern "C" void kernel_launch(void* const* d_in, const int* in_sizes, int n_in,
                              void* d_out, int out_size)
{
    const float* x    = (const float*)d_in[0];
    const float* h    = (const float*)d_in[1];
    const float* We0  = (const float*)d_in[2];
    const float* be0  = (const float*)d_in[3];
    const float* We1  = (const float*)d_in[4];
    const float* be1  = (const float*)d_in[5];
    const float* Winf = (const float*)d_in[6];
    const float* binf = (const float*)d_in[7];
    const float* Wx0  = (const float*)d_in[8];
    const float* bx0  = (const float*)d_in[9];
    const float* Wx1  = (const float*)d_in[10];
    const float* bx1  = (const float*)d_in[11];
    const float* Wxo  = (const float*)d_in[12];
    const float* bxo  = (const float*)d_in[13];
    const float* Wh0  = (const float*)d_in[14];
    const float* bh0  = (const float*)d_in[15];
    const float* Wh1  = (const float*)d_in[16];
    const float* bh1  = (const float*)d_in[17];
    const float* Who  = (const float*)d_in[18];
    const float* bho  = (const float*)d_in[19];
    float* out = (float*)d_out;

    node_pre_kernel<<<NN, 256>>>(x, h, We0);

    const int smem_floats =
        EG * SAPAD + MDIM * SATPAD + KSTAGE * SWPAD + 8 * MDIM + MDIM * 8 +
        MDIM + 4 * MDIM + 8 + TI * MDIM + EG * NH + 96 + 384 + EG + EG * NH + 96;
    const int smem_bytes = smem_floats * 4;
    static int attr_set = 0;
    if (!attr_set) {
        cudaFuncSetAttribute(edge_kernel, cudaFuncAttributeMaxDynamicSharedMemorySize, smem_bytes);
        attr_set = 1;
    }
    edge_kernel<<<dim3(NN / TI, JS), 256, smem_bytes>>>(
        x, We0, be0, We1, be1, Winf, binf, Wx0, bx0, Wx1, bx1, Wxo, bxo);

    finalize_x_kernel<<<(NN * NH * 3 + 255) / 256, 256>>>(x, out);

    h_kernel<<<NN / NPB, 256>>>(h, Wh0, bh0, Wh1, bh1, Who, bho, out);
}